// round 12
// baseline (speedup 1.0000x reference)
#include <cuda_runtime.h>
#include <cuda_fp16.h>
#include <stdint.h>
#include <string.h>

// Problem constants
#define IN_F   2048
#define OUTF   512
#define NB     8
#define BATCH  16

// Packed bits: g_pkw[fb32][out*8+lane] : uint32. Bit j holds the binarized
// weight for f = fb32*32 + j, column out*8+lane. Independent of batch.
// Dims: 64 x 4096 = 262144 words = 1 MB.
__device__ uint32_t g_pkw[64 * 4096];

static __device__ __forceinline__ __half2 u2h2(uint32_t u) {
    __half2 h; memcpy(&h, &u, 4); return h;
}
static __device__ __forceinline__ uint32_t h22u(__half2 h) {
    uint32_t u; memcpy(&u, &h, 4); return u;
}

// ---------------------------------------------------------------------------
// Pack kernel: binarize weight (>= 0.5), 1 bit per f, 32 f per word.
// idx = fb32*4096 + col. Adjacent threads read adjacent columns -> coalesced.
// ---------------------------------------------------------------------------
__global__ void pack_kernel(const float* __restrict__ w) {
    int idx = blockIdx.x * blockDim.x + threadIdx.x;
    int fb32 = idx >> 12;
    int col  = idx & 4095;
    uint32_t word = 0;
#pragma unroll
    for (int j = 0; j < 32; j++) {
        float v = __ldg(w + (size_t)(fb32 * 32 + j) * 4096 + col);
        word |= (v >= 0.5f ? 1u : 0u) << j;
    }
    g_pkw[idx] = word;
}

// ---------------------------------------------------------------------------
// Scan kernel: R6 execution shape + R9 short-chain step.
// Thread = lane k (0..7) of row-pair {b0, b0+8}; state = one half2 packing
// the two batch rows. 8 threads per row-pair; 1024 warps = 2 warps/SMSP on
// 128 SMs (the sibling warp fills the shfl-exposure window).
// CSA step: 6 fp16 fma-class ops (bit-identical per-lane sequence to R9-R11,
// rel_err canary 0.0006271157):
//   a  = xu & m
//   ga = fma(a,-2,1)
//   r  = fma(s, ga, a)       xor(s,a)     (s -> r : 4 cyc)
//   m1 = s*a
//   mj = fma(c, r, m1)       maj(s,a,c)
//   gc = fma(c,-2,1)
//   s' = fma(r, gc, c)       xor(r,c)     (r -> s' : 4 cyc)
// Carry: c[k](i+1) = mj[k-1](i): one shfl per step, lane-0 zeroed by mask.
// ---------------------------------------------------------------------------
__global__ void __launch_bounds__(256, 1)
scan_kernel(const float* __restrict__ x, float* __restrict__ out) {
    __shared__ uint32_t sx[IN_F];   // {half(x[b0,f]), half(x[b0+8,f])}

    const int tid = threadIdx.x;
    const int blk = blockIdx.x;
    const int b0 = blk >> 4;                 // 0..7 ; pair row is b0+8
    const int out_base = (blk & 15) << 5;    // 32 outs per block

    const float* xa = x + b0 * IN_F;
    const float* xb = x + (b0 + 8) * IN_F;
#pragma unroll
    for (int i = 0; i < IN_F / 256; i++) {
        int k = tid + i * 256;
        __half ha = __float2half(xa[k]);     // matches jnp astype(float16)
        __half hb = __float2half(xb[k]);
        sx[k] = h22u(__halves2half2(ha, hb));
    }
    __syncthreads();

    const int sub  = tid & 7;                // lane k within row-pair
    const int lane = tid & 31;
    const int srcl = sub ? (lane - 1) : lane;       // carry source lane
    const uint32_t zmask = sub ? 0xFFFFFFFFu : 0u;  // zero lane-0 carry-in
    const uint32_t* pk = g_pkw + out_base * 8 + tid;   // + fb32*4096 per chunk
    const __half2 neg2 = __float2half2_rn(-2.0f);
    const __half2 one  = __float2half2_rn(1.0f);
    const __half2 zero = __float2half2_rn(0.0f);

    uint32_t w = __ldg(pk);

    // Start from (s=0, c=0): a step from (0,0) yields exactly (s=a, c=0), so
    // f=0 is a regular step (fma(0,ga,a)=a, mj=0*... exact).
    __half2 s = zero;
    __half2 c = zero;

    auto step = [&](uint32_t wv, int j, uint32_t xu) {
        uint32_t m = (uint32_t)(((int32_t)(wv << (31 - j))) >> 31);
        __half2 a  = u2h2(xu & m);
        __half2 ga = __hfma2(a, neg2, one);
        __half2 r  = __hfma2(s, ga, a);      // xor(s, a)
        __half2 m1 = __hmul2(s, a);
        __half2 mj = __hfma2(c, r, m1);      // maj(s, a, c)
        __half2 gc = __hfma2(c, neg2, one);
        s = __hfma2(r, gc, c);               // xor(r, c)
        uint32_t prev = __shfl_sync(0xFFFFFFFFu, h22u(mj), srcl);
        c = u2h2(prev & zmask);
    };

    const uint4* sx4 = reinterpret_cast<const uint4*>(sx);

#pragma unroll 1
    for (int fb32 = 0; fb32 < 64; fb32++) {
        uint32_t wnext = 0;
        if (fb32 < 63) wnext = __ldg(pk + (fb32 + 1) * 4096);
        const uint4* p = sx4 + fb32 * 8;
#pragma unroll
        for (int jj = 0; jj < 8; jj++) {
            uint4 q = p[jj];
            step(w, 4 * jj + 0, q.x);
            step(w, 4 * jj + 1, q.y);
            step(w, 4 * jj + 2, q.z);
            step(w, 4 * jj + 3, q.w);
        }
        w = wnext;
    }

    // Output float32. Fully coalesced: block's threads cover 256 consecutive
    // (out,lane) slots. s at out[b*4096 + o*8 + k], c at +65536 floats.
    const int obase = b0 * 4096 + out_base * 8 + tid;
    float2 sf = __half22float2(s);   // .x = row b0, .y = row b0+8
    float2 cf = __half22float2(c);
    out[obase]                 = sf.x;
    out[obase + 32768]         = sf.y;
    out[65536 + obase]         = cf.x;
    out[65536 + obase + 32768] = cf.y;
}

// ---------------------------------------------------------------------------
extern "C" void kernel_launch(void* const* d_in, const int* in_sizes, int n_in,
                              void* d_out, int out_size) {
    const float* x  = (const float*)d_in[0];   // (16, 2048) fp32
    const float* wt = (const float*)d_in[1];   // (2048, 4096) fp32
    float* out = (float*)d_out;                // 131072 fp32: [s | c]

    pack_kernel<<<1024, 256>>>(wt);
    scan_kernel<<<128, 256>>>(x, out);
}